// round 13
// baseline (speedup 1.0000x reference)
#include <cuda_runtime.h>
#include <cuda_bf16.h>
#include <math.h>

// ---------------------------------------------------------------------------
// Scratch layout (floats):
//   y0: [4,160,160,64] NHWC   off 0
//   y1: [4, 80, 80,64]        off 6553600
//   y2: [4, 40, 40,64]        off 8192000
//   y3: [4, 20, 20,64]        off 8601600
//   X : [4,160,160,64]        off 8704000
//   om: [4,160,160,27]        off 15257600
//   Wt: [k][c][o]             off 18022400   (36864)
//   OWT:[kk][tap][c]          off 18059264   (15552)
// ---------------------------------------------------------------------------
#define OFF_Y0 0
#define OFF_Y1 6553600
#define OFF_Y2 8192000
#define OFF_Y3 8601600
#define OFF_X  8704000
#define OFF_OM 15257600
#define OFF_WT 18022400
#define OFF_OWT 18059264
#define SCRATCH_TOTAL 18074880

__device__ __align__(16) float g_scratch[SCRATCH_TOTAL];

// ---------------------------------------------------------------------------
// f32x2 packed-math helpers
// ---------------------------------------------------------------------------
typedef unsigned long long u64t;
__device__ __forceinline__ u64t fma2(u64t a, u64t b, u64t c) {
    u64t d;
    asm("fma.rn.f32x2 %0, %1, %2, %3;" : "=l"(d) : "l"(a), "l"(b), "l"(c));
    return d;
}
__device__ __forceinline__ u64t pack2(float lo, float hi) {
    u64t d; asm("mov.b64 %0, {%1, %2};" : "=l"(d) : "f"(lo), "f"(hi)); return d;
}
__device__ __forceinline__ float2 unpack2(u64t v) {
    float2 r; asm("mov.b64 {%0, %1}, %2;" : "=f"(r.x), "=f"(r.y) : "l"(v)); return r;
}

// ---------------------------------------------------------------------------
// Kernel 0: init — dcn wtrans + offconv weight transpose + bias pre-fill
// ---------------------------------------------------------------------------
__global__ void init_kernel(const float* __restrict__ dw,
                            const float* __restrict__ ow,
                            const float* __restrict__ g1, const float* __restrict__ b1,
                            const float* __restrict__ m1, const float* __restrict__ v1,
                            const float* __restrict__ g2, const float* __restrict__ b2,
                            const float* __restrict__ m2, const float* __restrict__ v2,
                            const float* __restrict__ g3, const float* __restrict__ b3,
                            const float* __restrict__ m3, const float* __restrict__ v3) {
    int bxi = blockIdx.x;
    int tid = threadIdx.x;
    if (bxi < 144) {
        int i = bxi * 256 + tid;           // 36864
        int o   = i & 63;
        int row = i >> 6;                  // k*64 + c
        int k   = row >> 6;
        int c   = row & 63;
        g_scratch[OFF_WT + i] = dw[(size_t)o * 576 + c * 9 + k];
        return;
    }
    if (bxi < 205) {
        int i = (bxi - 144) * 256 + tid;   // 15552
        if (i < 15552) {
            int kk   = i / 576;
            int rest = i - kk * 576;
            int tap  = rest >> 6;
            int c    = rest & 63;
            g_scratch[OFF_OWT + i] = ow[(size_t)kk * 576 + c * 9 + tap];
        }
        return;
    }
    size_t idx = (size_t)(bxi - 205) * 256 + tid;  // 0 .. 2150400
    int c = (int)(idx & 63);
    const float *g, *b, *m, *v;
    size_t off;
    if (idx < 1638400)      { g = g1; b = b1; m = m1; v = v1; off = OFF_Y1 + idx; }
    else if (idx < 2048000) { g = g2; b = b2; m = m2; v = v2; off = OFF_Y2 + (idx - 1638400); }
    else if (idx < 2150400) { g = g3; b = b3; m = m3; v = v3; off = OFF_Y3 + (idx - 2048000); }
    else return;
    float sc = __ldg(g + c) * rsqrtf(__ldg(v + c) + 1e-5f);
    g_scratch[off] = __ldg(b + c) - __ldg(m + c) * sc;
}

// ---------------------------------------------------------------------------
// Kernel 1: ALL 1x1 conv + BN levels in ONE launch
// ---------------------------------------------------------------------------
__global__ __launch_bounds__(256) void conv_all(
    const float* __restrict__ f0, const float* __restrict__ f1,
    const float* __restrict__ f2, const float* __restrict__ f3,
    const float* __restrict__ w0, const float* __restrict__ w1,
    const float* __restrict__ w2, const float* __restrict__ w3,
    const float* __restrict__ g0, const float* __restrict__ b0,
    const float* __restrict__ m0, const float* __restrict__ v0,
    const float* __restrict__ g1, const float* __restrict__ b1,
    const float* __restrict__ m1, const float* __restrict__ v1,
    const float* __restrict__ g2, const float* __restrict__ b2,
    const float* __restrict__ m2, const float* __restrict__ v2,
    const float* __restrict__ g3, const float* __restrict__ b3,
    const float* __restrict__ m3, const float* __restrict__ v3) {
    __shared__ __align__(16) float Wsh[16 * 68];
    __shared__ __align__(16) float Insh[16 * 64];

    int bx  = blockIdx.x;
    int bb  = blockIdx.y;
    int tid = threadIdx.x;

    int pxblk, ks, cin, HW, nsplit;
    const float *f, *w, *g, *b, *m, *v;
    float* y;
    if (bx < 400) {
        pxblk = bx; ks = 0; cin = 64; HW = 25600; nsplit = 1;
        f = f0; w = w0; g = g0; b = b0; m = m0; v = v0; y = g_scratch + OFF_Y0;
    } else if (bx < 600) {
        int t = bx - 400; pxblk = t >> 1; ks = t & 1; cin = 128; HW = 6400; nsplit = 2;
        f = f1; w = w1; g = g1; b = b1; m = m1; v = v1; y = g_scratch + OFF_Y1;
    } else if (bx < 700) {
        int t = bx - 600; pxblk = t >> 2; ks = t & 3; cin = 256; HW = 1600; nsplit = 4;
        f = f2; w = w2; g = g2; b = b2; m = m2; v = v2; y = g_scratch + OFF_Y2;
    } else {
        int t = bx - 700; pxblk = t >> 3; ks = t & 7; cin = 512; HW = 400; nsplit = 8;
        f = f3; w = w3; g = g3; b = b3; m = m3; v = v3; y = g_scratch + OFF_Y3;
    }

    int hw0 = pxblk * 64;
    const float* fb = f + (size_t)bb * cin * HW;

    int tx = tid & 15;
    int ty = tid >> 4;
    float acc[4][4];
    #pragma unroll
    for (int j = 0; j < 4; j++)
        #pragma unroll
        for (int i = 0; i < 4; i++) acc[j][i] = 0.f;

    int kbase = ks * 64;
    #pragma unroll 1
    for (int k0 = kbase; k0 < kbase + 64; k0 += 16) {
        {
            int c  = tid >> 2;
            int kt = (tid & 3) * 4;
            float4 wv = *(const float4*)(w + (size_t)c * cin + k0 + kt);
            Wsh[(kt + 0) * 68 + c] = wv.x;
            Wsh[(kt + 1) * 68 + c] = wv.y;
            Wsh[(kt + 2) * 68 + c] = wv.z;
            Wsh[(kt + 3) * 68 + c] = wv.w;
        }
        {
            int kt = tid >> 4;
            int p  = (tid & 15) * 4;
            float4 iv = make_float4(0.f, 0.f, 0.f, 0.f);
            if (hw0 + p < HW)
                iv = *(const float4*)(fb + (size_t)(k0 + kt) * HW + hw0 + p);
            *(float4*)(Insh + kt * 64 + p) = iv;
        }
        __syncthreads();
        #pragma unroll
        for (int kt = 0; kt < 16; kt++) {
            float4 wv = *(const float4*)(Wsh + kt * 68 + ty * 4);
            float4 xv = *(const float4*)(Insh + kt * 64 + tx * 4);
            acc[0][0] += xv.x * wv.x; acc[0][1] += xv.x * wv.y;
            acc[0][2] += xv.x * wv.z; acc[0][3] += xv.x * wv.w;
            acc[1][0] += xv.y * wv.x; acc[1][1] += xv.y * wv.y;
            acc[1][2] += xv.y * wv.z; acc[1][3] += xv.y * wv.w;
            acc[2][0] += xv.z * wv.x; acc[2][1] += xv.z * wv.y;
            acc[2][2] += xv.z * wv.z; acc[2][3] += xv.z * wv.w;
            acc[3][0] += xv.w * wv.x; acc[3][1] += xv.w * wv.y;
            acc[3][2] += xv.w * wv.z; acc[3][3] += xv.w * wv.w;
        }
        __syncthreads();
    }

    int cb = ty * 4;
    float sc[4], bi[4];
    #pragma unroll
    for (int i = 0; i < 4; i++) {
        sc[i] = __ldg(g + cb + i) * rsqrtf(__ldg(v + cb + i) + 1e-5f);
        bi[i] = __ldg(b + cb + i) - __ldg(m + cb + i) * sc[i];
    }
    if (nsplit == 1) {
        #pragma unroll
        for (int j = 0; j < 4; j++) {
            int hw = hw0 + tx * 4 + j;
            float4 ov;
            ov.x = acc[j][0] * sc[0] + bi[0];
            ov.y = acc[j][1] * sc[1] + bi[1];
            ov.z = acc[j][2] * sc[2] + bi[2];
            ov.w = acc[j][3] * sc[3] + bi[3];
            *(float4*)(y + ((size_t)bb * HW + hw) * 64 + cb) = ov;
        }
    } else {
        #pragma unroll
        for (int j = 0; j < 4; j++) {
            int hw = hw0 + tx * 4 + j;
            if (hw < HW) {
                float* yp = y + ((size_t)bb * HW + hw) * 64 + cb;
                #pragma unroll
                for (int i = 0; i < 4; i++)
                    atomicAdd(yp + i, acc[j][i] * sc[i]);
            }
        }
    }
}

// ---------------------------------------------------------------------------
// Kernel 2: fused bilinear upsample + sum + relu
// ---------------------------------------------------------------------------
__device__ __forceinline__ float4 bilerp4(const float* __restrict__ y,
                                          int bb, int n, int h, int w, int c) {
    float r  = (float)(n - 1) / 159.0f;
    float sy = (float)h * r;
    float sx = (float)w * r;
    int iy = (int)sy; if (iy > n - 2) iy = n - 2;
    int ix = (int)sx; if (ix > n - 2) ix = n - 2;
    float ty = sy - (float)iy;
    float tx = sx - (float)ix;
    const float* base = y + ((((size_t)bb * n + iy) * n + ix) * 64) + c;
    float4 v00 = *(const float4*)(base);
    float4 v01 = *(const float4*)(base + 64);
    float4 v10 = *(const float4*)(base + (size_t)n * 64);
    float4 v11 = *(const float4*)(base + (size_t)n * 64 + 64);
    float4 o;
    o.x = (v00.x * (1.f - tx) + v01.x * tx) * (1.f - ty) + (v10.x * (1.f - tx) + v11.x * tx) * ty;
    o.y = (v00.y * (1.f - tx) + v01.y * tx) * (1.f - ty) + (v10.y * (1.f - tx) + v11.y * tx) * ty;
    o.z = (v00.z * (1.f - tx) + v01.z * tx) * (1.f - ty) + (v10.z * (1.f - tx) + v11.z * tx) * ty;
    o.w = (v00.w * (1.f - tx) + v01.w * tx) * (1.f - ty) + (v10.w * (1.f - tx) + v11.w * tx) * ty;
    return o;
}

__global__ __launch_bounds__(256) void fuse_v2() {
    int tid = threadIdx.x;
    int c4  = (tid & 15) * 4;
    int pix = blockIdx.x * 16 + (tid >> 4);
    int bb  = pix / 25600;
    int hw  = pix - bb * 25600;
    int h   = hw / 160;
    int w   = hw - h * 160;
    const float* y0 = g_scratch + OFF_Y0;
    float4 a = *(const float4*)(y0 + (size_t)pix * 64 + c4);
    float4 t;
    t = bilerp4(g_scratch + OFF_Y1, bb, 80, h, w, c4); a.x += t.x; a.y += t.y; a.z += t.z; a.w += t.w;
    t = bilerp4(g_scratch + OFF_Y2, bb, 40, h, w, c4); a.x += t.x; a.y += t.y; a.z += t.z; a.w += t.w;
    t = bilerp4(g_scratch + OFF_Y3, bb, 20, h, w, c4); a.x += t.x; a.y += t.y; a.z += t.z; a.w += t.w;
    a.x = fmaxf(a.x, 0.f); a.y = fmaxf(a.y, 0.f);
    a.z = fmaxf(a.z, 0.f); a.w = fmaxf(a.w, 0.f);
    *(float4*)(g_scratch + OFF_X + (size_t)pix * 64 + c4) = a;
}

// ---------------------------------------------------------------------------
// Kernel 3: offset conv, channel-SIMD f32x2 with HOISTED staging index math.
// Per-thread slot tables computed once; chunk loop staging = LDG+STS only
// (source offsets are affine in c0). Inner compute identical to v5.
// ---------------------------------------------------------------------------
__global__ __launch_bounds__(128) void offconv_v6(const float* __restrict__ ob) {
    __shared__ __align__(16) float wbuf[27 * 74];    // ~8KB
    __shared__ __align__(16) float pbuf[34 * 3 * 8]; // 816 floats

    int tid = threadIdx.x;
    int w0  = blockIdx.x * 32;
    int h   = blockIdx.y;
    int bb  = blockIdx.z;
    const float* X   = g_scratch + OFF_X;
    const float* owt = g_scratch + OFF_OWT;
    float*       om  = g_scratch + OFF_OM;

    int kk = tid & 31;
    int p0 = (tid >> 5) * 8;

    // ---- hoisted staging tables (computed once) ----
    int dstW[16], srcW[16];
    #pragma unroll
    for (int s = 0; s < 16; s++) {
        int i = tid + s * 128;
        if (i < 1944) {
            int k2 = i / 72;
            int r2 = i - k2 * 72;          // tap*8 + cc
            dstW[s] = k2 * 74 + r2;
            srcW[s] = k2 * 576 + (r2 >> 3) * 64 + (r2 & 7);
        } else {
            dstW[s] = -1; srcW[s] = 0;
        }
    }
    int srcP[7];
    #pragma unroll
    for (int s = 0; s < 7; s++) {
        int i = tid + s * 128;
        if (i < 816) {
            int cc  = i & 7;
            int q   = i >> 3;              // col*3 + r
            int r   = q % 3;
            int col = q / 3;
            int hh = h + r - 1;
            int ww = w0 + col - 1;
            srcP[s] = (hh >= 0 && hh < 160 && ww >= 0 && ww < 160)
                      ? (((bb * 160 + hh) * 160 + ww) * 64 + cc) : -1;
        } else srcP[s] = -1;
    }

    u64t acc2[8];
    #pragma unroll
    for (int j = 0; j < 8; j++) acc2[j] = pack2(0.f, 0.f);

    #pragma unroll 1
    for (int c0 = 0; c0 < 64; c0 += 8) {
        // stage weights (hoisted offsets, src affine in c0)
        #pragma unroll
        for (int s = 0; s < 16; s++)
            if (dstW[s] >= 0) wbuf[dstW[s]] = __ldg(owt + srcW[s] + c0);
        // stage patch
        #pragma unroll
        for (int s = 0; s < 7; s++) {
            int i = tid + s * 128;
            if (i < 816) pbuf[i] = (srcP[s] >= 0) ? __ldg(X + srcP[s] + c0) : 0.f;
        }
        __syncthreads();

        if (kk < 27) {
            const float* wr = wbuf + kk * 74;
            #pragma unroll
            for (int r = 0; r < 3; r++) {
                #pragma unroll
                for (int cp = 0; cp < 4; cp++) {
                    u64t w20 = *(const u64t*)(wr + (r * 3 + 0) * 8 + cp * 2);
                    u64t w21 = *(const u64t*)(wr + (r * 3 + 1) * 8 + cp * 2);
                    u64t w22 = *(const u64t*)(wr + (r * 3 + 2) * 8 + cp * 2);
                    u64t in2[10];
                    #pragma unroll
                    for (int t = 0; t < 10; t++)
                        in2[t] = *(const u64t*)(pbuf + ((p0 + t) * 3 + r) * 8 + cp * 2);
                    #pragma unroll
                    for (int j = 0; j < 8; j++) {
                        acc2[j] = fma2(in2[j],     w20, acc2[j]);
                        acc2[j] = fma2(in2[j + 1], w21, acc2[j]);
                        acc2[j] = fma2(in2[j + 2], w22, acc2[j]);
                    }
                }
            }
        }
        __syncthreads();
    }

    if (kk < 27) {
        float bias = __ldg(ob + kk);
        size_t obase = ((((size_t)bb * 160 + h) * 160) + (w0 + p0)) * 27 + kk;
        #pragma unroll
        for (int j = 0; j < 8; j++) {
            float2 u = unpack2(acc2[j]);
            om[obase + (size_t)j * 27] = u.x + u.y + bias;
        }
    }
}

// ---------------------------------------------------------------------------
// Kernel 4: DCNv2, SPLIT-K over the 9 taps (round-8 v4 — the 551µs config).
// ---------------------------------------------------------------------------
__global__ __launch_bounds__(128) void dcn_v4(const float* __restrict__ gf,
                                              const float* __restrict__ bfp,
                                              const float* __restrict__ mf,
                                              const float* __restrict__ vf,
                                              float* __restrict__ out) {
    __shared__ __align__(16) float ssy[288];
    __shared__ __align__(16) float ssx[288];
    __shared__ __align__(16) float smk[288];
    __shared__ __align__(16) float val[32 * 68];

    int tid = threadIdx.x;
    int w0  = blockIdx.x * 32;
    int h   = blockIdx.y;
    int bb  = blockIdx.z;
    const float* om = g_scratch + OFF_OM;

    for (int i = tid; i < 288; i += 128) {
        int p = i / 9, k = i - p * 9;
        size_t base = ((((size_t)bb * 160 + h) * 160) + (w0 + p)) * 27;
        float dy = om[base + 2 * k];
        float dx = om[base + 2 * k + 1];
        float mk = om[base + 18 + k];
        smk[i] = 1.f / (1.f + expf(-mk));
        ssy[i] = (float)h + (float)(k / 3 - 1) + dy;
        ssx[i] = (float)(w0 + p) + (float)(k % 3 - 1) + dx;
    }
    __syncthreads();

    int o0 = (tid & 15) * 4;
    int pb = (tid >> 4) * 4;
    u64t acc[4][2];
    #pragma unroll
    for (int j = 0; j < 4; j++) {
        acc[j][0] = pack2(0.f, 0.f);
        acc[j][1] = pack2(0.f, 0.f);
    }

    const float* Xb = g_scratch + OFF_X + (size_t)bb * 25600 * 64;
    const float* wt = g_scratch + OFF_WT;

    #pragma unroll 1
    for (int k = 0; k < 9; k++) {
        {
            int c4 = (tid & 15) * 4;
            #pragma unroll
            for (int p = tid >> 4; p < 32; p += 8) {
                float syv = ssy[p * 9 + k];
                float sxv = ssx[p * 9 + k];
                float mkv = smk[p * 9 + k];
                float fy = floorf(syv), fx = floorf(sxv);
                int iy = (int)fy, ix = (int)fx;
                float ty = syv - fy, tx = sxv - fx;
                float4 r = make_float4(0.f, 0.f, 0.f, 0.f);
                #pragma unroll
                for (int d2 = 0; d2 < 2; d2++) {
                    int yy = iy + d2;
                    float wy = d2 ? ty : (1.f - ty);
                    bool vy = (yy >= 0) && (yy < 160);
                    int cy = yy < 0 ? 0 : (yy > 159 ? 159 : yy);
                    #pragma unroll
                    for (int d3 = 0; d3 < 2; d3++) {
                        int xx = ix + d3;
                        float wx = d3 ? tx : (1.f - tx);
                        bool vx = (xx >= 0) && (xx < 160);
                        int cx = xx < 0 ? 0 : (xx > 159 ? 159 : xx);
                        float wgt = wy * wx * ((vy && vx) ? 1.f : 0.f);
                        float4 gv = __ldg((const float4*)(Xb + ((size_t)cy * 160 + cx) * 64 + c4));
                        r.x += gv.x * wgt; r.y += gv.y * wgt;
                        r.z += gv.z * wgt; r.w += gv.w * wgt;
                    }
                }
                r.x *= mkv; r.y *= mkv; r.z *= mkv; r.w *= mkv;
                *(float4*)(val + (size_t)p * 68 + c4) = r;
            }
        }
        __syncthreads();

        {
            const float* vrow = val + (size_t)pb * 68;
            const float* wk   = wt + (size_t)k * 4096 + o0;
            #pragma unroll 4
            for (int c = 0; c < 64; c++) {
                ulonglong2 wp = __ldg((const ulonglong2*)(wk + c * 64));
                float v0 = vrow[c];
                float v1 = vrow[68 + c];
                float v2 = vrow[136 + c];
                float v3 = vrow[204 + c];
                u64t P0 = pack2(v0, v0), P1 = pack2(v1, v1);
                u64t P2 = pack2(v2, v2), P3 = pack2(v3, v3);
                acc[0][0] = fma2(P0, wp.x, acc[0][0]); acc[0][1] = fma2(P0, wp.y, acc[0][1]);
                acc[1][0] = fma2(P1, wp.x, acc[1][0]); acc[1][1] = fma2(P1, wp.y, acc[1][1]);
                acc[2][0] = fma2(P2, wp.x, acc[2][0]); acc[2][1] = fma2(P2, wp.y, acc[2][1]);
                acc[3][0] = fma2(P3, wp.x, acc[3][0]); acc[3][1] = fma2(P3, wp.y, acc[3][1]);
            }
        }
        __syncthreads();
    }

    float rr[4][4];
    #pragma unroll
    for (int j = 0; j < 4; j++) {
        float2 u0 = unpack2(acc[j][0]);
        float2 u1 = unpack2(acc[j][1]);
        rr[j][0] = u0.x; rr[j][1] = u0.y; rr[j][2] = u1.x; rr[j][3] = u1.y;
    }

    #pragma unroll
    for (int i = 0; i < 4; i++) {
        int o = o0 + i;
        float sc = __ldg(gf + o) * rsqrtf(__ldg(vf + o) + 1e-5f);
        float bi = __ldg(bfp + o) - __ldg(mf + o) * sc;
        float4 ov;
        ov.x = fmaxf(rr[0][i] * sc + bi, 0.f);
        ov.y = fmaxf(rr[1][i] * sc + bi, 0.f);
        ov.z = fmaxf(rr[2][i] * sc + bi, 0.f);
        ov.w = fmaxf(rr[3][i] * sc + bi, 0.f);
        *(float4*)(out + ((size_t)bb * 64 + o) * 25600 + h * 160 + w0 + pb) = ov;
    }
}

// ---------------------------------------------------------------------------
// launch
// ---------------------------------------------------------------------------
extern "C" void kernel_launch(void* const* d_in, const int* in_sizes, int n_in,
                              void* d_out, int out_size) {
    const float* f0 = (const float*)d_in[0];
    const float* f1 = (const float*)d_in[1];
    const float* f2 = (const float*)d_in[2];
    const float* f3 = (const float*)d_in[3];
    const float* w0 = (const float*)d_in[4];
    const float* g0 = (const float*)d_in[5];
    const float* b0 = (const float*)d_in[6];
    const float* m0 = (const float*)d_in[7];
    const float* v0 = (const float*)d_in[8];
    const float* w1 = (const float*)d_in[9];
    const float* g1 = (const float*)d_in[10];
    const float* b1 = (const float*)d_in[11];
    const float* m1 = (const float*)d_in[12];
    const float* v1 = (const float*)d_in[13];
    const float* w2 = (const float*)d_in[14];
    const float* g2 = (const float*)d_in[15];
    const float* b2 = (const float*)d_in[16];
    const float* m2 = (const float*)d_in[17];
    const float* v2 = (const float*)d_in[18];
    const float* w3 = (const float*)d_in[19];
    const float* g3 = (const float*)d_in[20];
    const float* b3 = (const float*)d_in[21];
    const float* m3 = (const float*)d_in[22];
    const float* v3 = (const float*)d_in[23];
    const float* off_w = (const float*)d_in[24];
    const float* off_b = (const float*)d_in[25];
    const float* dcn_w = (const float*)d_in[26];
    const float* gf = (const float*)d_in[27];
    const float* bf = (const float*)d_in[28];
    const float* mf = (const float*)d_in[29];
    const float* vf = (const float*)d_in[30];
    float* out = (float*)d_out;

    // init: wtrans (144) + offconv transpose (61) + bias fill (8400)
    init_kernel<<<205 + 8400, 256>>>(dcn_w, off_w,
                                     g1, b1, m1, v1,
                                     g2, b2, m2, v2,
                                     g3, b3, m3, v3);

    // all conv1x1+BN levels, one launch
    conv_all<<<dim3(756, 4), 256>>>(f0, f1, f2, f3, w0, w1, w2, w3,
                                    g0, b0, m0, v0, g1, b1, m1, v1,
                                    g2, b2, m2, v2, g3, b3, m3, v3);

    // fused upsample + sum + relu
    fuse_v2<<<6400, 256>>>();

    // offset conv (hoisted staging)
    offconv_v6<<<dim3(5, 160, 4), 128>>>(off_b);

    // deformable conv + final BN + relu (round-8 v4)
    dcn_v4<<<dim3(5, 160, 4), 128>>>(gf, bf, mf, vf, out);
}

// round 16
// speedup vs baseline: 1.0023x; 1.0023x over previous
#include <cuda_runtime.h>
#include <cuda_bf16.h>
#include <math.h>

// ---------------------------------------------------------------------------
// Scratch layout (floats):
//   y0: [4,160,160,64] NHWC   off 0
//   y1: [4, 80, 80,64]        off 6553600
//   y2: [4, 40, 40,64]        off 8192000
//   y3: [4, 20, 20,64]        off 8601600
//   X : [4,160,160,64]        off 8704000
//   om: [4,160,160,27]        off 15257600
//   Wt: [k][c][o]             off 18022400   (36864)
//   OWT:[kk][tap][c]          off 18059264   (15552)
// ---------------------------------------------------------------------------
#define OFF_Y0 0
#define OFF_Y1 6553600
#define OFF_Y2 8192000
#define OFF_Y3 8601600
#define OFF_X  8704000
#define OFF_OM 15257600
#define OFF_WT 18022400
#define OFF_OWT 18059264
#define SCRATCH_TOTAL 18074880

__device__ __align__(16) float g_scratch[SCRATCH_TOTAL];

// ---------------------------------------------------------------------------
// f32x2 packed-math helpers
// ---------------------------------------------------------------------------
typedef unsigned long long u64t;
__device__ __forceinline__ u64t fma2(u64t a, u64t b, u64t c) {
    u64t d;
    asm("fma.rn.f32x2 %0, %1, %2, %3;" : "=l"(d) : "l"(a), "l"(b), "l"(c));
    return d;
}
__device__ __forceinline__ u64t pack2(float lo, float hi) {
    u64t d; asm("mov.b64 %0, {%1, %2};" : "=l"(d) : "f"(lo), "f"(hi)); return d;
}
__device__ __forceinline__ float2 unpack2(u64t v) {
    float2 r; asm("mov.b64 {%0, %1}, %2;" : "=f"(r.x), "=f"(r.y) : "l"(v)); return r;
}

// ---------------------------------------------------------------------------
// Kernel 0: init — dcn wtrans + offconv weight transpose + bias pre-fill
// ---------------------------------------------------------------------------
__global__ void init_kernel(const float* __restrict__ dw,
                            const float* __restrict__ ow,
                            const float* __restrict__ g1, const float* __restrict__ b1,
                            const float* __restrict__ m1, const float* __restrict__ v1,
                            const float* __restrict__ g2, const float* __restrict__ b2,
                            const float* __restrict__ m2, const float* __restrict__ v2,
                            const float* __restrict__ g3, const float* __restrict__ b3,
                            const float* __restrict__ m3, const float* __restrict__ v3) {
    int bxi = blockIdx.x;
    int tid = threadIdx.x;
    if (bxi < 144) {
        int i = bxi * 256 + tid;           // 36864
        int o   = i & 63;
        int row = i >> 6;                  // k*64 + c
        int k   = row >> 6;
        int c   = row & 63;
        g_scratch[OFF_WT + i] = dw[(size_t)o * 576 + c * 9 + k];
        return;
    }
    if (bxi < 205) {
        int i = (bxi - 144) * 256 + tid;   // 15552
        if (i < 15552) {
            int kk   = i / 576;
            int rest = i - kk * 576;
            int tap  = rest >> 6;
            int c    = rest & 63;
            g_scratch[OFF_OWT + i] = ow[(size_t)kk * 576 + c * 9 + tap];
        }
        return;
    }
    size_t idx = (size_t)(bxi - 205) * 256 + tid;  // 0 .. 2150400
    int c = (int)(idx & 63);
    const float *g, *b, *m, *v;
    size_t off;
    if (idx < 1638400)      { g = g1; b = b1; m = m1; v = v1; off = OFF_Y1 + idx; }
    else if (idx < 2048000) { g = g2; b = b2; m = m2; v = v2; off = OFF_Y2 + (idx - 1638400); }
    else if (idx < 2150400) { g = g3; b = b3; m = m3; v = v3; off = OFF_Y3 + (idx - 2048000); }
    else return;
    float sc = __ldg(g + c) * rsqrtf(__ldg(v + c) + 1e-5f);
    g_scratch[off] = __ldg(b + c) - __ldg(m + c) * sc;
}

// ---------------------------------------------------------------------------
// Kernel 1: ALL 1x1 conv + BN levels in ONE launch
// ---------------------------------------------------------------------------
__global__ __launch_bounds__(256) void conv_all(
    const float* __restrict__ f0, const float* __restrict__ f1,
    const float* __restrict__ f2, const float* __restrict__ f3,
    const float* __restrict__ w0, const float* __restrict__ w1,
    const float* __restrict__ w2, const float* __restrict__ w3,
    const float* __restrict__ g0, const float* __restrict__ b0,
    const float* __restrict__ m0, const float* __restrict__ v0,
    const float* __restrict__ g1, const float* __restrict__ b1,
    const float* __restrict__ m1, const float* __restrict__ v1,
    const float* __restrict__ g2, const float* __restrict__ b2,
    const float* __restrict__ m2, const float* __restrict__ v2,
    const float* __restrict__ g3, const float* __restrict__ b3,
    const float* __restrict__ m3, const float* __restrict__ v3) {
    __shared__ __align__(16) float Wsh[16 * 68];
    __shared__ __align__(16) float Insh[16 * 64];

    int bx  = blockIdx.x;
    int bb  = blockIdx.y;
    int tid = threadIdx.x;

    int pxblk, ks, cin, HW, nsplit;
    const float *f, *w, *g, *b, *m, *v;
    float* y;
    if (bx < 400) {
        pxblk = bx; ks = 0; cin = 64; HW = 25600; nsplit = 1;
        f = f0; w = w0; g = g0; b = b0; m = m0; v = v0; y = g_scratch + OFF_Y0;
    } else if (bx < 600) {
        int t = bx - 400; pxblk = t >> 1; ks = t & 1; cin = 128; HW = 6400; nsplit = 2;
        f = f1; w = w1; g = g1; b = b1; m = m1; v = v1; y = g_scratch + OFF_Y1;
    } else if (bx < 700) {
        int t = bx - 600; pxblk = t >> 2; ks = t & 3; cin = 256; HW = 1600; nsplit = 4;
        f = f2; w = w2; g = g2; b = b2; m = m2; v = v2; y = g_scratch + OFF_Y2;
    } else {
        int t = bx - 700; pxblk = t >> 3; ks = t & 7; cin = 512; HW = 400; nsplit = 8;
        f = f3; w = w3; g = g3; b = b3; m = m3; v = v3; y = g_scratch + OFF_Y3;
    }

    int hw0 = pxblk * 64;
    const float* fb = f + (size_t)bb * cin * HW;

    int tx = tid & 15;
    int ty = tid >> 4;
    float acc[4][4];
    #pragma unroll
    for (int j = 0; j < 4; j++)
        #pragma unroll
        for (int i = 0; i < 4; i++) acc[j][i] = 0.f;

    int kbase = ks * 64;
    #pragma unroll 1
    for (int k0 = kbase; k0 < kbase + 64; k0 += 16) {
        {
            int c  = tid >> 2;
            int kt = (tid & 3) * 4;
            float4 wv = *(const float4*)(w + (size_t)c * cin + k0 + kt);
            Wsh[(kt + 0) * 68 + c] = wv.x;
            Wsh[(kt + 1) * 68 + c] = wv.y;
            Wsh[(kt + 2) * 68 + c] = wv.z;
            Wsh[(kt + 3) * 68 + c] = wv.w;
        }
        {
            int kt = tid >> 4;
            int p  = (tid & 15) * 4;
            float4 iv = make_float4(0.f, 0.f, 0.f, 0.f);
            if (hw0 + p < HW)
                iv = *(const float4*)(fb + (size_t)(k0 + kt) * HW + hw0 + p);
            *(float4*)(Insh + kt * 64 + p) = iv;
        }
        __syncthreads();
        #pragma unroll
        for (int kt = 0; kt < 16; kt++) {
            float4 wv = *(const float4*)(Wsh + kt * 68 + ty * 4);
            float4 xv = *(const float4*)(Insh + kt * 64 + tx * 4);
            acc[0][0] += xv.x * wv.x; acc[0][1] += xv.x * wv.y;
            acc[0][2] += xv.x * wv.z; acc[0][3] += xv.x * wv.w;
            acc[1][0] += xv.y * wv.x; acc[1][1] += xv.y * wv.y;
            acc[1][2] += xv.y * wv.z; acc[1][3] += xv.y * wv.w;
            acc[2][0] += xv.z * wv.x; acc[2][1] += xv.z * wv.y;
            acc[2][2] += xv.z * wv.z; acc[2][3] += xv.z * wv.w;
            acc[3][0] += xv.w * wv.x; acc[3][1] += xv.w * wv.y;
            acc[3][2] += xv.w * wv.z; acc[3][3] += xv.w * wv.w;
        }
        __syncthreads();
    }

    int cb = ty * 4;
    float sc[4], bi[4];
    #pragma unroll
    for (int i = 0; i < 4; i++) {
        sc[i] = __ldg(g + cb + i) * rsqrtf(__ldg(v + cb + i) + 1e-5f);
        bi[i] = __ldg(b + cb + i) - __ldg(m + cb + i) * sc[i];
    }
    if (nsplit == 1) {
        #pragma unroll
        for (int j = 0; j < 4; j++) {
            int hw = hw0 + tx * 4 + j;
            float4 ov;
            ov.x = acc[j][0] * sc[0] + bi[0];
            ov.y = acc[j][1] * sc[1] + bi[1];
            ov.z = acc[j][2] * sc[2] + bi[2];
            ov.w = acc[j][3] * sc[3] + bi[3];
            *(float4*)(y + ((size_t)bb * HW + hw) * 64 + cb) = ov;
        }
    } else {
        #pragma unroll
        for (int j = 0; j < 4; j++) {
            int hw = hw0 + tx * 4 + j;
            if (hw < HW) {
                float* yp = y + ((size_t)bb * HW + hw) * 64 + cb;
                #pragma unroll
                for (int i = 0; i < 4; i++)
                    atomicAdd(yp + i, acc[j][i] * sc[i]);
            }
        }
    }
}

// ---------------------------------------------------------------------------
// Kernel 2: fused bilinear upsample + sum + relu
// ---------------------------------------------------------------------------
__device__ __forceinline__ float4 bilerp4(const float* __restrict__ y,
                                          int bb, int n, int h, int w, int c) {
    float r  = (float)(n - 1) / 159.0f;
    float sy = (float)h * r;
    float sx = (float)w * r;
    int iy = (int)sy; if (iy > n - 2) iy = n - 2;
    int ix = (int)sx; if (ix > n - 2) ix = n - 2;
    float ty = sy - (float)iy;
    float tx = sx - (float)ix;
    const float* base = y + ((((size_t)bb * n + iy) * n + ix) * 64) + c;
    float4 v00 = *(const float4*)(base);
    float4 v01 = *(const float4*)(base + 64);
    float4 v10 = *(const float4*)(base + (size_t)n * 64);
    float4 v11 = *(const float4*)(base + (size_t)n * 64 + 64);
    float4 o;
    o.x = (v00.x * (1.f - tx) + v01.x * tx) * (1.f - ty) + (v10.x * (1.f - tx) + v11.x * tx) * ty;
    o.y = (v00.y * (1.f - tx) + v01.y * tx) * (1.f - ty) + (v10.y * (1.f - tx) + v11.y * tx) * ty;
    o.z = (v00.z * (1.f - tx) + v01.z * tx) * (1.f - ty) + (v10.z * (1.f - tx) + v11.z * tx) * ty;
    o.w = (v00.w * (1.f - tx) + v01.w * tx) * (1.f - ty) + (v10.w * (1.f - tx) + v11.w * tx) * ty;
    return o;
}

__global__ __launch_bounds__(256) void fuse_v2() {
    int tid = threadIdx.x;
    int c4  = (tid & 15) * 4;
    int pix = blockIdx.x * 16 + (tid >> 4);
    int bb  = pix / 25600;
    int hw  = pix - bb * 25600;
    int h   = hw / 160;
    int w   = hw - h * 160;
    const float* y0 = g_scratch + OFF_Y0;
    float4 a = *(const float4*)(y0 + (size_t)pix * 64 + c4);
    float4 t;
    t = bilerp4(g_scratch + OFF_Y1, bb, 80, h, w, c4); a.x += t.x; a.y += t.y; a.z += t.z; a.w += t.w;
    t = bilerp4(g_scratch + OFF_Y2, bb, 40, h, w, c4); a.x += t.x; a.y += t.y; a.z += t.z; a.w += t.w;
    t = bilerp4(g_scratch + OFF_Y3, bb, 20, h, w, c4); a.x += t.x; a.y += t.y; a.z += t.z; a.w += t.w;
    a.x = fmaxf(a.x, 0.f); a.y = fmaxf(a.y, 0.f);
    a.z = fmaxf(a.z, 0.f); a.w = fmaxf(a.w, 0.f);
    *(float4*)(g_scratch + OFF_X + (size_t)pix * 64 + c4) = a;
}

// ---------------------------------------------------------------------------
// Kernel 3: offset conv, channel-SIMD f32x2 with HOISTED staging index math.
// Per-thread slot tables computed once; chunk loop staging = LDG+STS only
// (source offsets are affine in c0). Inner compute identical to v5.
// ---------------------------------------------------------------------------
__global__ __launch_bounds__(128) void offconv_v6(const float* __restrict__ ob) {
    __shared__ __align__(16) float wbuf[27 * 74];    // ~8KB
    __shared__ __align__(16) float pbuf[34 * 3 * 8]; // 816 floats

    int tid = threadIdx.x;
    int w0  = blockIdx.x * 32;
    int h   = blockIdx.y;
    int bb  = blockIdx.z;
    const float* X   = g_scratch + OFF_X;
    const float* owt = g_scratch + OFF_OWT;
    float*       om  = g_scratch + OFF_OM;

    int kk = tid & 31;
    int p0 = (tid >> 5) * 8;

    // ---- hoisted staging tables (computed once) ----
    int dstW[16], srcW[16];
    #pragma unroll
    for (int s = 0; s < 16; s++) {
        int i = tid + s * 128;
        if (i < 1944) {
            int k2 = i / 72;
            int r2 = i - k2 * 72;          // tap*8 + cc
            dstW[s] = k2 * 74 + r2;
            srcW[s] = k2 * 576 + (r2 >> 3) * 64 + (r2 & 7);
        } else {
            dstW[s] = -1; srcW[s] = 0;
        }
    }
    int srcP[7];
    #pragma unroll
    for (int s = 0; s < 7; s++) {
        int i = tid + s * 128;
        if (i < 816) {
            int cc  = i & 7;
            int q   = i >> 3;              // col*3 + r
            int r   = q % 3;
            int col = q / 3;
            int hh = h + r - 1;
            int ww = w0 + col - 1;
            srcP[s] = (hh >= 0 && hh < 160 && ww >= 0 && ww < 160)
                      ? (((bb * 160 + hh) * 160 + ww) * 64 + cc) : -1;
        } else srcP[s] = -1;
    }

    u64t acc2[8];
    #pragma unroll
    for (int j = 0; j < 8; j++) acc2[j] = pack2(0.f, 0.f);

    #pragma unroll 1
    for (int c0 = 0; c0 < 64; c0 += 8) {
        // stage weights (hoisted offsets, src affine in c0)
        #pragma unroll
        for (int s = 0; s < 16; s++)
            if (dstW[s] >= 0) wbuf[dstW[s]] = __ldg(owt + srcW[s] + c0);
        // stage patch
        #pragma unroll
        for (int s = 0; s < 7; s++) {
            int i = tid + s * 128;
            if (i < 816) pbuf[i] = (srcP[s] >= 0) ? __ldg(X + srcP[s] + c0) : 0.f;
        }
        __syncthreads();

        if (kk < 27) {
            const float* wr = wbuf + kk * 74;
            #pragma unroll
            for (int r = 0; r < 3; r++) {
                #pragma unroll
                for (int cp = 0; cp < 4; cp++) {
                    u64t w20 = *(const u64t*)(wr + (r * 3 + 0) * 8 + cp * 2);
                    u64t w21 = *(const u64t*)(wr + (r * 3 + 1) * 8 + cp * 2);
                    u64t w22 = *(const u64t*)(wr + (r * 3 + 2) * 8 + cp * 2);
                    u64t in2[10];
                    #pragma unroll
                    for (int t = 0; t < 10; t++)
                        in2[t] = *(const u64t*)(pbuf + ((p0 + t) * 3 + r) * 8 + cp * 2);
                    #pragma unroll
                    for (int j = 0; j < 8; j++) {
                        acc2[j] = fma2(in2[j],     w20, acc2[j]);
                        acc2[j] = fma2(in2[j + 1], w21, acc2[j]);
                        acc2[j] = fma2(in2[j + 2], w22, acc2[j]);
                    }
                }
            }
        }
        __syncthreads();
    }

    if (kk < 27) {
        float bias = __ldg(ob + kk);
        size_t obase = ((((size_t)bb * 160 + h) * 160) + (w0 + p0)) * 27 + kk;
        #pragma unroll
        for (int j = 0; j < 8; j++) {
            float2 u = unpack2(acc2[j]);
            om[obase + (size_t)j * 27] = u.x + u.y + bias;
        }
    }
}

// ---------------------------------------------------------------------------
// Kernel 4: DCNv2, SPLIT-K over the 9 taps (round-8 v4 — the 551µs config).
// ---------------------------------------------------------------------------
__global__ __launch_bounds__(128) void dcn_v4(const float* __restrict__ gf,
                                              const float* __restrict__ bfp,
                                              const float* __restrict__ mf,
                                              const float* __restrict__ vf,
                                              float* __restrict__ out) {
    __shared__ __align__(16) float ssy[288];
    __shared__ __align__(16) float ssx[288];
    __shared__ __align__(16) float smk[288];
    __shared__ __align__(16) float val[32 * 68];

    int tid = threadIdx.x;
    int w0  = blockIdx.x * 32;
    int h   = blockIdx.y;
    int bb  = blockIdx.z;
    const float* om = g_scratch + OFF_OM;

    for (int i = tid; i < 288; i += 128) {
        int p = i / 9, k = i - p * 9;
        size_t base = ((((size_t)bb * 160 + h) * 160) + (w0 + p)) * 27;
        float dy = om[base + 2 * k];
        float dx = om[base + 2 * k + 1];
        float mk = om[base + 18 + k];
        smk[i] = 1.f / (1.f + expf(-mk));
        ssy[i] = (float)h + (float)(k / 3 - 1) + dy;
        ssx[i] = (float)(w0 + p) + (float)(k % 3 - 1) + dx;
    }
    __syncthreads();

    int o0 = (tid & 15) * 4;
    int pb = (tid >> 4) * 4;
    u64t acc[4][2];
    #pragma unroll
    for (int j = 0; j < 4; j++) {
        acc[j][0] = pack2(0.f, 0.f);
        acc[j][1] = pack2(0.f, 0.f);
    }

    const float* Xb = g_scratch + OFF_X + (size_t)bb * 25600 * 64;
    const float* wt = g_scratch + OFF_WT;

    #pragma unroll 1
    for (int k = 0; k < 9; k++) {
        {
            int c4 = (tid & 15) * 4;
            #pragma unroll
            for (int p = tid >> 4; p < 32; p += 8) {
                float syv = ssy[p * 9 + k];
                float sxv = ssx[p * 9 + k];
                float mkv = smk[p * 9 + k];
                float fy = floorf(syv), fx = floorf(sxv);
                int iy = (int)fy, ix = (int)fx;
                float ty = syv - fy, tx = sxv - fx;
                float4 r = make_float4(0.f, 0.f, 0.f, 0.f);
                #pragma unroll
                for (int d2 = 0; d2 < 2; d2++) {
                    int yy = iy + d2;
                    float wy = d2 ? ty : (1.f - ty);
                    bool vy = (yy >= 0) && (yy < 160);
                    int cy = yy < 0 ? 0 : (yy > 159 ? 159 : yy);
                    #pragma unroll
                    for (int d3 = 0; d3 < 2; d3++) {
                        int xx = ix + d3;
                        float wx = d3 ? tx : (1.f - tx);
                        bool vx = (xx >= 0) && (xx < 160);
                        int cx = xx < 0 ? 0 : (xx > 159 ? 159 : xx);
                        float wgt = wy * wx * ((vy && vx) ? 1.f : 0.f);
                        float4 gv = __ldg((const float4*)(Xb + ((size_t)cy * 160 + cx) * 64 + c4));
                        r.x += gv.x * wgt; r.y += gv.y * wgt;
                        r.z += gv.z * wgt; r.w += gv.w * wgt;
                    }
                }
                r.x *= mkv; r.y *= mkv; r.z *= mkv; r.w *= mkv;
                *(float4*)(val + (size_t)p * 68 + c4) = r;
            }
        }
        __syncthreads();

        {
            const float* vrow = val + (size_t)pb * 68;
            const float* wk   = wt + (size_t)k * 4096 + o0;
            #pragma unroll 4
            for (int c = 0; c < 64; c++) {
                ulonglong2 wp = __ldg((const ulonglong2*)(wk + c * 64));
                float v0 = vrow[c];
                float v1 = vrow[68 + c];
                float v2 = vrow[136 + c];
                float v3 = vrow[204 + c];
                u64t P0 = pack2(v0, v0), P1 = pack2(v1, v1);
                u64t P2 = pack2(v2, v2), P3 = pack2(v3, v3);
                acc[0][0] = fma2(P0, wp.x, acc[0][0]); acc[0][1] = fma2(P0, wp.y, acc[0][1]);
                acc[1][0] = fma2(P1, wp.x, acc[1][0]); acc[1][1] = fma2(P1, wp.y, acc[1][1]);
                acc[2][0] = fma2(P2, wp.x, acc[2][0]); acc[2][1] = fma2(P2, wp.y, acc[2][1]);
                acc[3][0] = fma2(P3, wp.x, acc[3][0]); acc[3][1] = fma2(P3, wp.y, acc[3][1]);
            }
        }
        __syncthreads();
    }

    float rr[4][4];
    #pragma unroll
    for (int j = 0; j < 4; j++) {
        float2 u0 = unpack2(acc[j][0]);
        float2 u1 = unpack2(acc[j][1]);
        rr[j][0] = u0.x; rr[j][1] = u0.y; rr[j][2] = u1.x; rr[j][3] = u1.y;
    }

    #pragma unroll
    for (int i = 0; i < 4; i++) {
        int o = o0 + i;
        float sc = __ldg(gf + o) * rsqrtf(__ldg(vf + o) + 1e-5f);
        float bi = __ldg(bfp + o) - __ldg(mf + o) * sc;
        float4 ov;
        ov.x = fmaxf(rr[0][i] * sc + bi, 0.f);
        ov.y = fmaxf(rr[1][i] * sc + bi, 0.f);
        ov.z = fmaxf(rr[2][i] * sc + bi, 0.f);
        ov.w = fmaxf(rr[3][i] * sc + bi, 0.f);
        *(float4*)(out + ((size_t)bb * 64 + o) * 25600 + h * 160 + w0 + pb) = ov;
    }
}

// ---------------------------------------------------------------------------
// launch
// ---------------------------------------------------------------------------
extern "C" void kernel_launch(void* const* d_in, const int* in_sizes, int n_in,
                              void* d_out, int out_size) {
    const float* f0 = (const float*)d_in[0];
    const float* f1 = (const float*)d_in[1];
    const float* f2 = (const float*)d_in[2];
    const float* f3 = (const float*)d_in[3];
    const float* w0 = (const float*)d_in[4];
    const float* g0 = (const float*)d_in[5];
    const float* b0 = (const float*)d_in[6];
    const float* m0 = (const float*)d_in[7];
    const float* v0 = (const float*)d_in[8];
    const float* w1 = (const float*)d_in[9];
    const float* g1 = (const float*)d_in[10];
    const float* b1 = (const float*)d_in[11];
    const float* m1 = (const float*)d_in[12];
    const float* v1 = (const float*)d_in[13];
    const float* w2 = (const float*)d_in[14];
    const float* g2 = (const float*)d_in[15];
    const float* b2 = (const float*)d_in[16];
    const float* m2 = (const float*)d_in[17];
    const float* v2 = (const float*)d_in[18];
    const float* w3 = (const float*)d_in[19];
    const float* g3 = (const float*)d_in[20];
    const float* b3 = (const float*)d_in[21];
    const float* m3 = (const float*)d_in[22];
    const float* v3 = (const float*)d_in[23];
    const float* off_w = (const float*)d_in[24];
    const float* off_b = (const float*)d_in[25];
    const float* dcn_w = (const float*)d_in[26];
    const float* gf = (const float*)d_in[27];
    const float* bf = (const float*)d_in[28];
    const float* mf = (const float*)d_in[29];
    const float* vf = (const float*)d_in[30];
    float* out = (float*)d_out;

    // init: wtrans (144) + offconv transpose (61) + bias fill (8400)
    init_kernel<<<205 + 8400, 256>>>(dcn_w, off_w,
                                     g1, b1, m1, v1,
                                     g2, b2, m2, v2,
                                     g3, b3, m3, v3);

    // all conv1x1+BN levels, one launch
    conv_all<<<dim3(756, 4), 256>>>(f0, f1, f2, f3, w0, w1, w2, w3,
                                    g0, b0, m0, v0, g1, b1, m1, v1,
                                    g2, b2, m2, v2, g3, b3, m3, v3);

    // fused upsample + sum + relu
    fuse_v2<<<6400, 256>>>();

    // offset conv (hoisted staging)
    offconv_v6<<<dim3(5, 160, 4), 128>>>(off_b);

    // deformable conv + final BN + relu (round-8 v4)
    dcn_v4<<<dim3(5, 160, 4), 128>>>(gf, bf, mf, vf, out);
}